// round 1
// baseline (speedup 1.0000x reference)
#include <cuda_runtime.h>
#include <cstdint>

#define BB 32
#define SS 2048
#define EE 128
#define HH 8
#define DD 16
#define HD 128
#define KTOT 132
#define CACHE 256
#define WINDOW 128
#define SINKS 4

// d_out layout: [output (B*S*HD)] [new_k (B*H*128*16)] [new_v (B*H*128*16)]
#define OUT_ELEMS (BB * SS * HD)            // 8388608
#define KOFF OUT_ELEMS                      // 8388608
#define VOFF (KOFF + BB * HH * WINDOW * DD) // 8912896

// ---------------- scratch (device globals; no allocation APIs) ----------------
__device__ float    g_q[(size_t)BB * HH * SS * DD];   // 33.5 MB, layout (b,h,s,d)
__device__ float    g_ao[(size_t)BB * SS * HD];       // 33.5 MB, layout (b,s,h*d)
__device__ unsigned g_wq[4][32 * 128];                // packed ternary weights (q,k,v,o)
__device__ float    g_ws[4];                          // w_scale per weight
__device__ unsigned g_amax_x;
__device__ unsigned g_amax_o;

// ---------------- helpers ----------------
__device__ __forceinline__ unsigned quant4(float4 v, float is) {
    // round-half-even, IEEE divide => bit-match jnp.round(x / i_scale)
    int a = (int)fminf(fmaxf(rintf(__fdiv_rn(v.x, is)), -128.f), 127.f);
    int b = (int)fminf(fmaxf(rintf(__fdiv_rn(v.y, is)), -128.f), 127.f);
    int c = (int)fminf(fmaxf(rintf(__fdiv_rn(v.z, is)), -128.f), 127.f);
    int d = (int)fminf(fmaxf(rintf(__fdiv_rn(v.w, is)), -128.f), 127.f);
    return (unsigned)(a & 0xFF) | ((unsigned)(b & 0xFF) << 8) |
           ((unsigned)(c & 0xFF) << 16) | ((unsigned)(d & 0xFF) << 24);
}

// ---------------- kernel 0: reset atomics ----------------
__global__ void k_init() { g_amax_x = 0u; g_amax_o = 0u; }

// ---------------- kernel 1: w_scale + ternarize + pack (4 blocks) -------------
__global__ __launch_bounds__(256) void k_prep(const float* qw, const float* kw,
                                              const float* vw, const float* ow) {
    int bw = blockIdx.x;
    const float* w = (bw == 0) ? qw : (bw == 1) ? kw : (bw == 2) ? vw : ow;
    __shared__ float red[256];
    __shared__ float ws_s;
    int t = threadIdx.x;
    float s = 0.f;
    for (int i = t; i < 16384; i += 256) s += fabsf(w[i]);
    red[t] = s;
    __syncthreads();
    for (int o = 128; o > 0; o >>= 1) {
        if (t < o) red[t] += red[t + o];
        __syncthreads();
    }
    if (t == 0) { ws_s = red[0] / 16384.0f; g_ws[bw] = ws_s; }
    __syncthreads();
    float thr = 0.5f * ws_s;
    int c = t >> 1, half = t & 1;
    for (int i = 0; i < 16; i++) {
        int kk = half * 16 + i;
        float4 wv = *(const float4*)(w + c * 128 + kk * 4);
        int t0 = (fabsf(wv.x) > thr) ? (wv.x > 0.f ? 1 : -1) : 0;
        int t1 = (fabsf(wv.y) > thr) ? (wv.y > 0.f ? 1 : -1) : 0;
        int t2 = (fabsf(wv.z) > thr) ? (wv.z > 0.f ? 1 : -1) : 0;
        int t3 = (fabsf(wv.w) > thr) ? (wv.w > 0.f ? 1 : -1) : 0;
        unsigned p = (unsigned)(t0 & 0xFF) | ((unsigned)(t1 & 0xFF) << 8) |
                     ((unsigned)(t2 & 0xFF) << 16) | ((unsigned)(t3 & 0xFF) << 24);
        g_wq[bw][kk * 128 + c] = p;
    }
}

// ---------------- kernel 2: abs-max over x ----------------
__global__ __launch_bounds__(256) void k_amax(const float* x, int n4) {
    int idx = blockIdx.x * blockDim.x + threadIdx.x;
    int stride = gridDim.x * blockDim.x;
    float m = 0.f;
    const float4* x4 = (const float4*)x;
    for (int i = idx; i < n4; i += stride) {
        float4 v = x4[i];
        m = fmaxf(m, fmaxf(fmaxf(fabsf(v.x), fabsf(v.y)), fmaxf(fabsf(v.z), fabsf(v.w))));
    }
    for (int o = 16; o; o >>= 1) m = fmaxf(m, __shfl_xor_sync(0xFFFFFFFFu, m, o));
    if ((threadIdx.x & 31) == 0) atomicMax(&g_amax_x, __float_as_uint(m));
}

// ---------------- shared GEMM core: 32 rows x 128 cols, dp4a ----------------
// 256 threads. warp w owns rows 4w..4w+3; lane owns cols {lane, lane+32, lane+64, lane+96}
__device__ __forceinline__ void bitgemm_core(const float* xbase, const unsigned* wq_g,
                                             float is, unsigned* xq_s, unsigned* wq_s,
                                             int (&acc)[4][4]) {
    int t = threadIdx.x;
    {
        int row = t >> 3, seg = t & 7;
        const float4* src = (const float4*)(xbase + row * 128 + seg * 16);
        uint4 pk;
        pk.x = quant4(src[0], is);
        pk.y = quant4(src[1], is);
        pk.z = quant4(src[2], is);
        pk.w = quant4(src[3], is);
        *(uint4*)(xq_s + row * 32 + seg * 4) = pk;
    }
    {
        const uint4* src = (const uint4*)wq_g;
        uint4* dst = (uint4*)wq_s;
#pragma unroll
        for (int i = 0; i < 4; i++) dst[t + i * 256] = src[t + i * 256];
    }
    __syncthreads();
    int warp = t >> 5, lane = t & 31;
#pragma unroll
    for (int rr = 0; rr < 4; rr++)
#pragma unroll
        for (int cc = 0; cc < 4; cc++) acc[rr][cc] = 0;
#pragma unroll 8
    for (int kk = 0; kk < 32; kk++) {
        int x0 = (int)xq_s[(warp * 4 + 0) * 32 + kk];
        int x1 = (int)xq_s[(warp * 4 + 1) * 32 + kk];
        int x2 = (int)xq_s[(warp * 4 + 2) * 32 + kk];
        int x3 = (int)xq_s[(warp * 4 + 3) * 32 + kk];
        int w0 = (int)wq_s[kk * 128 + lane];
        int w1 = (int)wq_s[kk * 128 + lane + 32];
        int w2 = (int)wq_s[kk * 128 + lane + 64];
        int w3 = (int)wq_s[kk * 128 + lane + 96];
        acc[0][0] = __dp4a(x0, w0, acc[0][0]);
        acc[0][1] = __dp4a(x0, w1, acc[0][1]);
        acc[0][2] = __dp4a(x0, w2, acc[0][2]);
        acc[0][3] = __dp4a(x0, w3, acc[0][3]);
        acc[1][0] = __dp4a(x1, w0, acc[1][0]);
        acc[1][1] = __dp4a(x1, w1, acc[1][1]);
        acc[1][2] = __dp4a(x1, w2, acc[1][2]);
        acc[1][3] = __dp4a(x1, w3, acc[1][3]);
        acc[2][0] = __dp4a(x2, w0, acc[2][0]);
        acc[2][1] = __dp4a(x2, w1, acc[2][1]);
        acc[2][2] = __dp4a(x2, w2, acc[2][2]);
        acc[2][3] = __dp4a(x2, w3, acc[2][3]);
        acc[3][0] = __dp4a(x3, w0, acc[3][0]);
        acc[3][1] = __dp4a(x3, w1, acc[3][1]);
        acc[3][2] = __dp4a(x3, w2, acc[3][2]);
        acc[3][3] = __dp4a(x3, w3, acc[3][3]);
    }
}

// ---------------- kernel 3: Q projection (all 65536 rows) ----------------
__global__ __launch_bounds__(256) void k_qproj(const float* x, const float* qb) {
    __shared__ unsigned xq_s[32 * 32];
    __shared__ unsigned wq_s[32 * 128];
    int row0 = blockIdx.x * 32;
    float is = __fdiv_rn(__uint_as_float(g_amax_x), 127.0f);
    float sc = g_ws[0] * is;
    int acc[4][4];
    bitgemm_core(x + (size_t)row0 * 128, g_wq[0], is, xq_s, wq_s, acc);
    int warp = threadIdx.x >> 5, lane = threadIdx.x & 31;
#pragma unroll
    for (int rr = 0; rr < 4; rr++) {
        int r = row0 + warp * 4 + rr;
        int b = r >> 11, s = r & 2047;
#pragma unroll
        for (int cc = 0; cc < 4; cc++) {
            int c = lane + 32 * cc;
            int h = c >> 4, d = c & 15;
            float v = (float)acc[rr][cc] * sc + qb[c];
            g_q[(((size_t)(b * HH + h)) * SS + s) * DD + d] = v;
        }
    }
}

// ---------------- kernel 4: K/V projection (last 128 tokens/batch) ----------
// grid.x = 128 (row blocks of 32 over 4096 rows), grid.y: 0 = K, 1 = V
__global__ __launch_bounds__(256) void k_kvproj(const float* x, const float* kb,
                                                const float* vb, float* out) {
    __shared__ unsigned xq_s[32 * 32];
    __shared__ unsigned wq_s[32 * 128];
    int which = blockIdx.y;  // 0: K, 1: V
    int row0 = blockIdx.x * 32;  // r in [0,4096): b = r>>7, i = r&127
    int b = row0 >> 7, i0 = row0 & 127;
    const float* xbase = x + (((size_t)b * SS) + (SS - WINDOW) + i0) * EE;
    float is = __fdiv_rn(__uint_as_float(g_amax_x), 127.0f);
    float sc = g_ws[1 + which] * is;
    const float* bias = which ? vb : kb;
    size_t base = which ? (size_t)VOFF : (size_t)KOFF;
    int acc[4][4];
    bitgemm_core(xbase, g_wq[1 + which], is, xq_s, wq_s, acc);
    int warp = threadIdx.x >> 5, lane = threadIdx.x & 31;
#pragma unroll
    for (int rr = 0; rr < 4; rr++) {
        int r = row0 + warp * 4 + rr;
        int b2 = r >> 7, ii = r & 127;
#pragma unroll
        for (int cc = 0; cc < 4; cc++) {
            int c = lane + 32 * cc;
            int h = c >> 4, d = c & 15;
            float v = (float)acc[rr][cc] * sc + bias[c];
            out[base + (((size_t)(b2 * HH + h)) * WINDOW + ii) * DD + d] = v;
        }
    }
}

// ---------------- kernel 5: attention + fused abs-max of output -------------
// grid: (8 query chunks of 256, H, B); one thread per query, online softmax
__global__ __launch_bounds__(256) void k_attn(const float* cached_k, const float* cached_v,
                                              const float* outbuf) {
    __shared__ float ks[KTOT * DD];
    __shared__ float vs[KTOT * DD];
    int b = blockIdx.z, h = blockIdx.y, chunk = blockIdx.x;
    int t = threadIdx.x;
    size_t bh = (size_t)(b * HH + h);
    const float* knew = outbuf + KOFF + bh * WINDOW * DD;
    const float* vnew = outbuf + VOFF + bh * WINDOW * DD;
    const float* kc = cached_k + bh * CACHE * DD;
    const float* vc = cached_v + bh * CACHE * DD;
    for (int i = t; i < KTOT * DD; i += 256) {
        int j = i >> 4;
        ks[i] = (j < SINKS) ? kc[i] : knew[i - SINKS * DD];
        vs[i] = (j < SINKS) ? vc[i] : vnew[i - SINKS * DD];
    }
    __syncthreads();

    int s = chunk * 256 + t;
    const float4* qp = (const float4*)(g_q + (bh * SS + s) * DD);
    float4 q0 = qp[0], q1 = qp[1], q2 = qp[2], q3 = qp[3];
    int jmax = min(s, KTOT - 1);

    float m = __int_as_float(0xff800000);  // -inf
    float l = 0.f;
    float4 a0 = {0, 0, 0, 0}, a1 = {0, 0, 0, 0}, a2 = {0, 0, 0, 0}, a3 = {0, 0, 0, 0};
    const float4* k4 = (const float4*)ks;
    const float4* v4 = (const float4*)vs;
    for (int j = 0; j <= jmax; j++) {
        float4 ka = k4[j * 4 + 0], kb2 = k4[j * 4 + 1];
        float4 kc2 = k4[j * 4 + 2], kd = k4[j * 4 + 3];
        float p0 = fmaf(q0.x, ka.x, fmaf(q0.y, ka.y, fmaf(q0.z, ka.z, q0.w * ka.w)));
        float p1 = fmaf(q1.x, kb2.x, fmaf(q1.y, kb2.y, fmaf(q1.z, kb2.z, q1.w * kb2.w)));
        float p2 = fmaf(q2.x, kc2.x, fmaf(q2.y, kc2.y, fmaf(q2.z, kc2.z, q2.w * kc2.w)));
        float p3 = fmaf(q3.x, kd.x, fmaf(q3.y, kd.y, fmaf(q3.z, kd.z, q3.w * kd.w)));
        float sc = ((p0 + p1) + (p2 + p3)) * 0.25f;
        float4 va = v4[j * 4 + 0], vb2 = v4[j * 4 + 1];
        float4 vc2 = v4[j * 4 + 2], vd = v4[j * 4 + 3];
        if (sc > m) {
            float r = __expf(m - sc);  // first iter: exp(-inf)=0
            l = fmaf(l, r, 1.0f);
            a0.x = fmaf(a0.x, r, va.x);  a0.y = fmaf(a0.y, r, va.y);
            a0.z = fmaf(a0.z, r, va.z);  a0.w = fmaf(a0.w, r, va.w);
            a1.x = fmaf(a1.x, r, vb2.x); a1.y = fmaf(a1.y, r, vb2.y);
            a1.z = fmaf(a1.z, r, vb2.z); a1.w = fmaf(a1.w, r, vb2.w);
            a2.x = fmaf(a2.x, r, vc2.x); a2.y = fmaf(a2.y, r, vc2.y);
            a2.z = fmaf(a2.z, r, vc2.z); a2.w = fmaf(a2.w, r, vc2.w);
            a3.x = fmaf(a3.x, r, vd.x);  a3.y = fmaf(a3.y, r, vd.y);
            a3.z = fmaf(a3.z, r, vd.z);  a3.w = fmaf(a3.w, r, vd.w);
            m = sc;
        } else {
            float p = __expf(sc - m);
            l += p;
            a0.x = fmaf(p, va.x, a0.x);  a0.y = fmaf(p, va.y, a0.y);
            a0.z = fmaf(p, va.z, a0.z);  a0.w = fmaf(p, va.w, a0.w);
            a1.x = fmaf(p, vb2.x, a1.x); a1.y = fmaf(p, vb2.y, a1.y);
            a1.z = fmaf(p, vb2.z, a1.z); a1.w = fmaf(p, vb2.w, a1.w);
            a2.x = fmaf(p, vc2.x, a2.x); a2.y = fmaf(p, vc2.y, a2.y);
            a2.z = fmaf(p, vc2.z, a2.z); a2.w = fmaf(p, vc2.w, a2.w);
            a3.x = fmaf(p, vd.x, a3.x);  a3.y = fmaf(p, vd.y, a3.y);
            a3.z = fmaf(p, vd.z, a3.z);  a3.w = fmaf(p, vd.w, a3.w);
        }
    }
    float inv = 1.0f / l;
    a0.x *= inv; a0.y *= inv; a0.z *= inv; a0.w *= inv;
    a1.x *= inv; a1.y *= inv; a1.z *= inv; a1.w *= inv;
    a2.x *= inv; a2.y *= inv; a2.z *= inv; a2.w *= inv;
    a3.x *= inv; a3.y *= inv; a3.z *= inv; a3.w *= inv;

    float4* op = (float4*)(g_ao + ((size_t)b * SS + s) * HD + h * DD);
    op[0] = a0; op[1] = a1; op[2] = a2; op[3] = a3;

    float mx = fmaxf(fmaxf(fmaxf(fabsf(a0.x), fabsf(a0.y)), fmaxf(fabsf(a0.z), fabsf(a0.w))),
                     fmaxf(fmaxf(fabsf(a1.x), fabsf(a1.y)), fmaxf(fabsf(a1.z), fabsf(a1.w))));
    mx = fmaxf(mx, fmaxf(fmaxf(fabsf(a2.x), fabsf(a2.y)), fmaxf(fabsf(a2.z), fabsf(a2.w))));
    mx = fmaxf(mx, fmaxf(fmaxf(fabsf(a3.x), fabsf(a3.y)), fmaxf(fabsf(a3.z), fabsf(a3.w))));
    for (int o = 16; o; o >>= 1) mx = fmaxf(mx, __shfl_xor_sync(0xFFFFFFFFu, mx, o));
    if ((t & 31) == 0) atomicMax(&g_amax_o, __float_as_uint(mx));
}

// ---------------- kernel 6: O projection ----------------
__global__ __launch_bounds__(256) void k_oproj(const float* ob, float* out) {
    __shared__ unsigned xq_s[32 * 32];
    __shared__ unsigned wq_s[32 * 128];
    int row0 = blockIdx.x * 32;
    float is = __fdiv_rn(__uint_as_float(g_amax_o), 127.0f);
    float sc = g_ws[3] * is;
    int acc[4][4];
    bitgemm_core(g_ao + (size_t)row0 * 128, g_wq[3], is, xq_s, wq_s, acc);
    int warp = threadIdx.x >> 5, lane = threadIdx.x & 31;
#pragma unroll
    for (int rr = 0; rr < 4; rr++) {
        int r = row0 + warp * 4 + rr;
#pragma unroll
        for (int cc = 0; cc < 4; cc++) {
            int c = lane + 32 * cc;
            out[(size_t)r * 128 + c] = (float)acc[rr][cc] * sc + ob[c];
        }
    }
}

// ---------------- launcher ----------------
extern "C" void kernel_launch(void* const* d_in, const int* in_sizes, int n_in,
                              void* d_out, int out_size) {
    const float* x  = (const float*)d_in[0];
    const float* ck = (const float*)d_in[1];
    const float* cv = (const float*)d_in[2];
    const float* qw = (const float*)d_in[3];
    const float* qb = (const float*)d_in[4];
    const float* kw = (const float*)d_in[5];
    const float* kb = (const float*)d_in[6];
    const float* vw = (const float*)d_in[7];
    const float* vb = (const float*)d_in[8];
    const float* ow = (const float*)d_in[9];
    const float* ob = (const float*)d_in[10];
    float* out = (float*)d_out;

    k_init<<<1, 1>>>();
    k_prep<<<4, 256>>>(qw, kw, vw, ow);
    k_amax<<<1024, 256>>>(x, (BB * SS * EE) / 4);
    k_qproj<<<(BB * SS) / 32, 256>>>(x, qb);
    k_kvproj<<<dim3((BB * WINDOW) / 32, 2), 256>>>(x, kb, vb, out);
    k_attn<<<dim3(SS / 256, HH, BB), 256>>>(ck, cv, out);
    k_oproj<<<(BB * SS) / 32, 256>>>(ob, out);
}

// round 2
// speedup vs baseline: 1.0381x; 1.0381x over previous
#include <cuda_runtime.h>
#include <cstdint>

#define BB 32
#define SS 2048
#define EE 128
#define HH 8
#define DD 16
#define HD 128
#define KTOT 132
#define CACHE 256
#define WINDOW 128
#define SINKS 4

// d_out layout: [output (B*S*HD)] [new_k (B*H*128*16)] [new_v (B*H*128*16)]
#define OUT_ELEMS (BB * SS * HD)            // 8388608
#define KOFF OUT_ELEMS                      // 8388608
#define VOFF (KOFF + BB * HH * WINDOW * DD) // 8912896

// ---------------- scratch (device globals; no allocation APIs) ----------------
__device__ float    g_q[(size_t)BB * SS * HD];        // 33.5 MB, layout (b,s,h*d)
__device__ float    g_ao[(size_t)BB * SS * HD];       // 33.5 MB, layout (b,s,h*d)
__device__ unsigned g_wq[4][32 * 128];                // packed ternary weights (q,k,v,o)
__device__ float    g_ws[4];                          // w_scale per weight
__device__ unsigned g_amax_x;
__device__ unsigned g_amax_o;

// ---------------- f32x2 packed-math helpers (sm_103a) ----------------
__device__ __forceinline__ unsigned long long f2_mul(unsigned long long a, unsigned long long b) {
    unsigned long long d;
    asm("mul.rn.f32x2 %0,%1,%2;" : "=l"(d) : "l"(a), "l"(b));
    return d;
}
__device__ __forceinline__ unsigned long long f2_fma(unsigned long long a, unsigned long long b,
                                                     unsigned long long c) {
    unsigned long long d;
    asm("fma.rn.f32x2 %0,%1,%2,%3;" : "=l"(d) : "l"(a), "l"(b), "l"(c));
    return d;
}
__device__ __forceinline__ unsigned long long f2_add(unsigned long long a, unsigned long long b) {
    unsigned long long d;
    asm("add.rn.f32x2 %0,%1,%2;" : "=l"(d) : "l"(a), "l"(b));
    return d;
}
__device__ __forceinline__ unsigned long long f2_pack(float lo, float hi) {
    unsigned long long d;
    asm("mov.b64 %0,{%1,%2};" : "=l"(d) : "f"(lo), "f"(hi));
    return d;
}
__device__ __forceinline__ float2 f2_unpack(unsigned long long v) {
    float2 r;
    asm("mov.b64 {%0,%1},%2;" : "=f"(r.x), "=f"(r.y) : "l"(v));
    return r;
}

// ---------------- helpers ----------------
__device__ __forceinline__ unsigned quant4(float4 v, float is_inv) {
    int a = __float2int_rn(fminf(fmaxf(v.x * is_inv, -128.f), 127.f));
    int b = __float2int_rn(fminf(fmaxf(v.y * is_inv, -128.f), 127.f));
    int c = __float2int_rn(fminf(fmaxf(v.z * is_inv, -128.f), 127.f));
    int d = __float2int_rn(fminf(fmaxf(v.w * is_inv, -128.f), 127.f));
    return (unsigned)(a & 0xFF) | ((unsigned)(b & 0xFF) << 8) |
           ((unsigned)(c & 0xFF) << 16) | ((unsigned)(d & 0xFF) << 24);
}

// ---------------- kernel 1: w_scale + ternarize + pack (4 blocks) + init -----
__global__ __launch_bounds__(256) void k_prep(const float* qw, const float* kw,
                                              const float* vw, const float* ow) {
    int bw = blockIdx.x;
    if (bw == 0 && threadIdx.x == 0) { g_amax_x = 0u; g_amax_o = 0u; }
    const float* w = (bw == 0) ? qw : (bw == 1) ? kw : (bw == 2) ? vw : ow;
    __shared__ float red[256];
    __shared__ float ws_s;
    int t = threadIdx.x;
    float s = 0.f;
    for (int i = t; i < 16384; i += 256) s += fabsf(w[i]);
    red[t] = s;
    __syncthreads();
    for (int o = 128; o > 0; o >>= 1) {
        if (t < o) red[t] += red[t + o];
        __syncthreads();
    }
    if (t == 0) { ws_s = red[0] / 16384.0f; g_ws[bw] = ws_s; }
    __syncthreads();
    float thr = 0.5f * ws_s;
    int c = t >> 1, half = t & 1;
    for (int i = 0; i < 16; i++) {
        int kk = half * 16 + i;
        float4 wv = *(const float4*)(w + c * 128 + kk * 4);
        int t0 = (fabsf(wv.x) > thr) ? (wv.x > 0.f ? 1 : -1) : 0;
        int t1 = (fabsf(wv.y) > thr) ? (wv.y > 0.f ? 1 : -1) : 0;
        int t2 = (fabsf(wv.z) > thr) ? (wv.z > 0.f ? 1 : -1) : 0;
        int t3 = (fabsf(wv.w) > thr) ? (wv.w > 0.f ? 1 : -1) : 0;
        unsigned p = (unsigned)(t0 & 0xFF) | ((unsigned)(t1 & 0xFF) << 8) |
                     ((unsigned)(t2 & 0xFF) << 16) | ((unsigned)(t3 & 0xFF) << 24);
        g_wq[bw][kk * 128 + c] = p;
    }
}

// ---------------- kernel 2: abs-max over x ----------------
__global__ __launch_bounds__(256) void k_amax(const float* x, int n4) {
    int idx = blockIdx.x * blockDim.x + threadIdx.x;
    int stride = gridDim.x * blockDim.x;
    float m = 0.f;
    const float4* x4 = (const float4*)x;
    for (int i = idx; i < n4; i += stride) {
        float4 v = x4[i];
        m = fmaxf(m, fmaxf(fmaxf(fabsf(v.x), fabsf(v.y)), fmaxf(fabsf(v.z), fabsf(v.w))));
    }
    for (int o = 16; o; o >>= 1) m = fmaxf(m, __shfl_xor_sync(0xFFFFFFFFu, m, o));
    if ((threadIdx.x & 31) == 0) atomicMax(&g_amax_x, __float_as_uint(m));
}

// ---------------- shared GEMM core: 32 rows x 128 cols, dp4a ----------------
// 256 threads. warp w owns rows 4w..4w+3; lane owns cols 4*lane..4*lane+3
#define DP(a, b, c) c = __dp4a((int)(a), (int)(b), c)

__device__ __forceinline__ void bitgemm_core(const float* xbase, const unsigned* wq_g,
                                             float is_inv, unsigned* xq_s, unsigned* wq_s,
                                             int (&acc)[4][4]) {
    int t = threadIdx.x;
    {
        int row = t >> 3, seg = t & 7;
        const float4* src = (const float4*)(xbase + row * 128 + seg * 16);
        uint4 pk;
        pk.x = quant4(src[0], is_inv);
        pk.y = quant4(src[1], is_inv);
        pk.z = quant4(src[2], is_inv);
        pk.w = quant4(src[3], is_inv);
        *(uint4*)(xq_s + row * 32 + seg * 4) = pk;
    }
    {
        const uint4* src = (const uint4*)wq_g;
        uint4* dst = (uint4*)wq_s;
#pragma unroll
        for (int i = 0; i < 4; i++) dst[t + i * 256] = src[t + i * 256];
    }
    __syncthreads();
    int warp = t >> 5, lane = t & 31;
#pragma unroll
    for (int rr = 0; rr < 4; rr++)
#pragma unroll
        for (int cc = 0; cc < 4; cc++) acc[rr][cc] = 0;
    const uint4* x4 = (const uint4*)xq_s;  // [row*8 + kk/4]
    const uint4* w4 = (const uint4*)wq_s;  // [kk*32 + lane] = cols 4l..4l+3 at word kk
#pragma unroll
    for (int kk = 0; kk < 32; kk += 4) {
        uint4 xr0 = x4[(warp * 4 + 0) * 8 + (kk >> 2)];
        uint4 xr1 = x4[(warp * 4 + 1) * 8 + (kk >> 2)];
        uint4 xr2 = x4[(warp * 4 + 2) * 8 + (kk >> 2)];
        uint4 xr3 = x4[(warp * 4 + 3) * 8 + (kk >> 2)];
        uint4 w0 = w4[(kk + 0) * 32 + lane];
        uint4 w1 = w4[(kk + 1) * 32 + lane];
        uint4 w2 = w4[(kk + 2) * 32 + lane];
        uint4 w3 = w4[(kk + 3) * 32 + lane];
        DP(xr0.x, w0.x, acc[0][0]); DP(xr0.y, w1.x, acc[0][0]); DP(xr0.z, w2.x, acc[0][0]); DP(xr0.w, w3.x, acc[0][0]);
        DP(xr0.x, w0.y, acc[0][1]); DP(xr0.y, w1.y, acc[0][1]); DP(xr0.z, w2.y, acc[0][1]); DP(xr0.w, w3.y, acc[0][1]);
        DP(xr0.x, w0.z, acc[0][2]); DP(xr0.y, w1.z, acc[0][2]); DP(xr0.z, w2.z, acc[0][2]); DP(xr0.w, w3.z, acc[0][2]);
        DP(xr0.x, w0.w, acc[0][3]); DP(xr0.y, w1.w, acc[0][3]); DP(xr0.z, w2.w, acc[0][3]); DP(xr0.w, w3.w, acc[0][3]);
        DP(xr1.x, w0.x, acc[1][0]); DP(xr1.y, w1.x, acc[1][0]); DP(xr1.z, w2.x, acc[1][0]); DP(xr1.w, w3.x, acc[1][0]);
        DP(xr1.x, w0.y, acc[1][1]); DP(xr1.y, w1.y, acc[1][1]); DP(xr1.z, w2.y, acc[1][1]); DP(xr1.w, w3.y, acc[1][1]);
        DP(xr1.x, w0.z, acc[1][2]); DP(xr1.y, w1.z, acc[1][2]); DP(xr1.z, w2.z, acc[1][2]); DP(xr1.w, w3.z, acc[1][2]);
        DP(xr1.x, w0.w, acc[1][3]); DP(xr1.y, w1.w, acc[1][3]); DP(xr1.z, w2.w, acc[1][3]); DP(xr1.w, w3.w, acc[1][3]);
        DP(xr2.x, w0.x, acc[2][0]); DP(xr2.y, w1.x, acc[2][0]); DP(xr2.z, w2.x, acc[2][0]); DP(xr2.w, w3.x, acc[2][0]);
        DP(xr2.x, w0.y, acc[2][1]); DP(xr2.y, w1.y, acc[2][1]); DP(xr2.z, w2.y, acc[2][1]); DP(xr2.w, w3.y, acc[2][1]);
        DP(xr2.x, w0.z, acc[2][2]); DP(xr2.y, w1.z, acc[2][2]); DP(xr2.z, w2.z, acc[2][2]); DP(xr2.w, w3.z, acc[2][2]);
        DP(xr2.x, w0.w, acc[2][3]); DP(xr2.y, w1.w, acc[2][3]); DP(xr2.z, w2.w, acc[2][3]); DP(xr2.w, w3.w, acc[2][3]);
        DP(xr3.x, w0.x, acc[3][0]); DP(xr3.y, w1.x, acc[3][0]); DP(xr3.z, w2.x, acc[3][0]); DP(xr3.w, w3.x, acc[3][0]);
        DP(xr3.x, w0.y, acc[3][1]); DP(xr3.y, w1.y, acc[3][1]); DP(xr3.z, w2.y, acc[3][1]); DP(xr3.w, w3.y, acc[3][1]);
        DP(xr3.x, w0.z, acc[3][2]); DP(xr3.y, w1.z, acc[3][2]); DP(xr3.z, w2.z, acc[3][2]); DP(xr3.w, w3.z, acc[3][2]);
        DP(xr3.x, w0.w, acc[3][3]); DP(xr3.y, w1.w, acc[3][3]); DP(xr3.z, w2.w, acc[3][3]); DP(xr3.w, w3.w, acc[3][3]);
    }
}

// ---------------- kernel 3: Q + K/V projections in one launch ----------------
// blocks [0, 2048): Q rows; [2048, 2176): K rows; [2176, 2304): V rows
__global__ __launch_bounds__(256) void k_proj(const float* x, const float* qb,
                                              const float* kb, const float* vb,
                                              float* out) {
    __shared__ unsigned xq_s[32 * 32];
    __shared__ unsigned wq_s[32 * 128];
    int blk = blockIdx.x;
    float amax = __uint_as_float(g_amax_x);
    float is_inv = __fdiv_rn(127.0f, amax);
    float is = amax * (1.0f / 127.0f);
    int warp = threadIdx.x >> 5, lane = threadIdx.x & 31;
    int c0 = lane * 4;
    int acc[4][4];

    if (blk < 2048) {  // ---- Q ----
        int row0 = blk * 32;
        float sc = g_ws[0] * is;
        bitgemm_core(x + (size_t)row0 * 128, g_wq[0], is_inv, xq_s, wq_s, acc);
        float4 bias = *(const float4*)(qb + c0);
#pragma unroll
        for (int rr = 0; rr < 4; rr++) {
            int r = row0 + warp * 4 + rr;
            float4 o;
            o.x = (float)acc[rr][0] * sc + bias.x;
            o.y = (float)acc[rr][1] * sc + bias.y;
            o.z = (float)acc[rr][2] * sc + bias.z;
            o.w = (float)acc[rr][3] * sc + bias.w;
            *(float4*)(g_q + (size_t)r * 128 + c0) = o;
        }
    } else {  // ---- K or V, last 128 tokens of each batch ----
        int which = (blk >= 2176) ? 1 : 0;
        int row0 = (blk - (which ? 2176 : 2048)) * 32;  // r in [0,4096)
        int b = row0 >> 7, i0 = row0 & 127;
        const float* xbase = x + (((size_t)b * SS) + (SS - WINDOW) + i0) * EE;
        float sc = g_ws[1 + which] * is;
        const float* bias_p = which ? vb : kb;
        size_t base = which ? (size_t)VOFF : (size_t)KOFF;
        bitgemm_core(xbase, g_wq[1 + which], is_inv, xq_s, wq_s, acc);
        float4 bias = *(const float4*)(bias_p + c0);
        int h = c0 >> 4, d0 = c0 & 15;
#pragma unroll
        for (int rr = 0; rr < 4; rr++) {
            int r = row0 + warp * 4 + rr;
            int b2 = r >> 7, ii = r & 127;
            float4 o;
            o.x = (float)acc[rr][0] * sc + bias.x;
            o.y = (float)acc[rr][1] * sc + bias.y;
            o.z = (float)acc[rr][2] * sc + bias.z;
            o.w = (float)acc[rr][3] * sc + bias.w;
            *(float4*)(out + base + (((size_t)(b2 * HH + h)) * WINDOW + ii) * DD + d0) = o;
        }
    }
}

// ---------------- kernel 5: attention (f32x2) + fused abs-max ----------------
// grid: (8 query chunks of 256, H, B); one thread per query, online softmax
__global__ __launch_bounds__(256) void k_attn(const float* cached_k, const float* cached_v,
                                              const float* outbuf) {
    __shared__ __align__(16) float ks[KTOT * DD];
    __shared__ __align__(16) float vs[KTOT * DD];
    int b = blockIdx.z, h = blockIdx.y, chunk = blockIdx.x;
    int t = threadIdx.x;
    size_t bh = (size_t)(b * HH + h);
    const float* knew = outbuf + KOFF + bh * WINDOW * DD;
    const float* vnew = outbuf + VOFF + bh * WINDOW * DD;
    const float* kc = cached_k + bh * CACHE * DD;
    const float* vc = cached_v + bh * CACHE * DD;
    for (int i = t; i < KTOT * DD; i += 256) {
        int j = i >> 4;
        ks[i] = (j < SINKS) ? kc[i] : knew[i - SINKS * DD];
        vs[i] = (j < SINKS) ? vc[i] : vnew[i - SINKS * DD];
    }
    __syncthreads();

    int s = chunk * 256 + t;
    const ulonglong2* qp = (const ulonglong2*)(g_q + ((size_t)b * SS + s) * HD + h * DD);
    unsigned long long q[8];
    {
        ulonglong2 q01 = qp[0], q23 = qp[1], q45 = qp[2], q67 = qp[3];
        q[0] = q01.x; q[1] = q01.y; q[2] = q23.x; q[3] = q23.y;
        q[4] = q45.x; q[5] = q45.y; q[6] = q67.x; q[7] = q67.y;
    }
    int jmax = min(s, KTOT - 1);

    float m = __int_as_float(0xff800000);  // -inf
    float l = 0.f;
    unsigned long long a[8];
#pragma unroll
    for (int i = 0; i < 8; i++) a[i] = 0ull;  // +0.0f pair
    const ulonglong2* k2 = (const ulonglong2*)ks;
    const ulonglong2* v2 = (const ulonglong2*)vs;
#pragma unroll 2
    for (int j = 0; j <= jmax; j++) {
        ulonglong2 kA = k2[j * 4 + 0], kB = k2[j * 4 + 1];
        ulonglong2 kC = k2[j * 4 + 2], kD = k2[j * 4 + 3];
        unsigned long long d0 = f2_mul(q[0], kA.x);
        unsigned long long d1 = f2_mul(q[1], kA.y);
        d0 = f2_fma(q[2], kB.x, d0);
        d1 = f2_fma(q[3], kB.y, d1);
        d0 = f2_fma(q[4], kC.x, d0);
        d1 = f2_fma(q[5], kC.y, d1);
        d0 = f2_fma(q[6], kD.x, d0);
        d1 = f2_fma(q[7], kD.y, d1);
        float2 ds = f2_unpack(f2_add(d0, d1));
        float sc = (ds.x + ds.y) * 0.25f;
        ulonglong2 vA = v2[j * 4 + 0], vB = v2[j * 4 + 1];
        ulonglong2 vC = v2[j * 4 + 2], vD = v2[j * 4 + 3];
        if (sc > m) {
            float r = __expf(m - sc);  // first iter: exp(-inf)=0
            unsigned long long r2 = f2_pack(r, r);
            l = fmaf(l, r, 1.0f);
            a[0] = f2_fma(a[0], r2, vA.x);
            a[1] = f2_fma(a[1], r2, vA.y);
            a[2] = f2_fma(a[2], r2, vB.x);
            a[3] = f2_fma(a[3], r2, vB.y);
            a[4] = f2_fma(a[4], r2, vC.x);
            a[5] = f2_fma(a[5], r2, vC.y);
            a[6] = f2_fma(a[6], r2, vD.x);
            a[7] = f2_fma(a[7], r2, vD.y);
            m = sc;
        } else {
            float p = __expf(sc - m);
            unsigned long long p2 = f2_pack(p, p);
            l += p;
            a[0] = f2_fma(p2, vA.x, a[0]);
            a[1] = f2_fma(p2, vA.y, a[1]);
            a[2] = f2_fma(p2, vB.x, a[2]);
            a[3] = f2_fma(p2, vB.y, a[3]);
            a[4] = f2_fma(p2, vC.x, a[4]);
            a[5] = f2_fma(p2, vC.y, a[5]);
            a[6] = f2_fma(p2, vD.x, a[6]);
            a[7] = f2_fma(p2, vD.y, a[7]);
        }
    }
    float inv = 1.0f / l;
    unsigned long long inv2 = f2_pack(inv, inv);
#pragma unroll
    for (int i = 0; i < 8; i++) a[i] = f2_mul(a[i], inv2);

    ulonglong2* op = (ulonglong2*)(g_ao + ((size_t)b * SS + s) * HD + h * DD);
    op[0] = make_ulonglong2(a[0], a[1]);
    op[1] = make_ulonglong2(a[2], a[3]);
    op[2] = make_ulonglong2(a[4], a[5]);
    op[3] = make_ulonglong2(a[6], a[7]);

    float mx = 0.f;
#pragma unroll
    for (int i = 0; i < 8; i++) {
        float2 u = f2_unpack(a[i]);
        mx = fmaxf(mx, fmaxf(fabsf(u.x), fabsf(u.y)));
    }
    for (int o = 16; o; o >>= 1) mx = fmaxf(mx, __shfl_xor_sync(0xFFFFFFFFu, mx, o));
    if ((t & 31) == 0) atomicMax(&g_amax_o, __float_as_uint(mx));
}

// ---------------- kernel 6: O projection ----------------
__global__ __launch_bounds__(256) void k_oproj(const float* ob, float* out) {
    __shared__ unsigned xq_s[32 * 32];
    __shared__ unsigned wq_s[32 * 128];
    int row0 = blockIdx.x * 32;
    float amax = __uint_as_float(g_amax_o);
    float is_inv = __fdiv_rn(127.0f, amax);
    float sc = g_ws[3] * (amax * (1.0f / 127.0f));
    int acc[4][4];
    bitgemm_core(g_ao + (size_t)row0 * 128, g_wq[3], is_inv, xq_s, wq_s, acc);
    int warp = threadIdx.x >> 5, lane = threadIdx.x & 31;
    int c0 = lane * 4;
    float4 bias = *(const float4*)(ob + c0);
#pragma unroll
    for (int rr = 0; rr < 4; rr++) {
        int r = row0 + warp * 4 + rr;
        float4 o;
        o.x = (float)acc[rr][0] * sc + bias.x;
        o.y = (float)acc[rr][1] * sc + bias.y;
        o.z = (float)acc[rr][2] * sc + bias.z;
        o.w = (float)acc[rr][3] * sc + bias.w;
        *(float4*)(out + (size_t)r * 128 + c0) = o;
    }
}

// ---------------- launcher ----------------
extern "C" void kernel_launch(void* const* d_in, const int* in_sizes, int n_in,
                              void* d_out, int out_size) {
    const float* x  = (const float*)d_in[0];
    const float* ck = (const float*)d_in[1];
    const float* cv = (const float*)d_in[2];
    const float* qb = (const float*)d_in[4];
    const float* kb = (const float*)d_in[6];
    const float* vb = (const float*)d_in[8];
    const float* ob = (const float*)d_in[10];
    const float* qw = (const float*)d_in[3];
    const float* kw = (const float*)d_in[5];
    const float* vw = (const float*)d_in[7];
    const float* ow = (const float*)d_in[9];
    float* out = (float*)d_out;

    k_prep<<<4, 256>>>(qw, kw, vw, ow);
    k_amax<<<1024, 256>>>(x, (BB * SS * EE) / 4);
    k_proj<<<2048 + 256, 256>>>(x, qb, kb, vb, out);
    k_attn<<<dim3(SS / 256, HH, BB), 256>>>(ck, cv, out);
    k_oproj<<<(BB * SS) / 32, 256>>>(ob, out);
}